// round 13
// baseline (speedup 1.0000x reference)
#include <cuda_runtime.h>
#include <cstdint>
#include <math.h>

// ---------------------------------------------------------------------------
// Qwen3 attention block. Round 13: BK=64 2-stage GEMM ring, 64 barriers/CTA
// (was 128). Loop order [wait_group 0 -> barrier -> prefetch(t+1) ->
// compute(t)] makes one barrier serve both publish(t) and free((t+1)&1).
// Flash: R11 GQA. Side-stream w_o overlap kept. Norm/prepass unchanged.
// ---------------------------------------------------------------------------

#define T_SEQ 2048
#define HID   4096
#define NQH   32
#define NKV   8
#define HD    128
#define QKV_N 6144
#define O_N   4096

__device__ float g_qkv[(size_t)T_SEQ * QKV_N];
__device__ float g_attn[(size_t)T_SEQ * O_N];
__device__ float g_hidr[(size_t)T_SEQ * HID];
__device__ float g_wqkvr[(size_t)HID * QKV_N];
__device__ float g_wor[(size_t)HID * O_N];

__device__ __forceinline__ float f2tf32(float x) {
    uint32_t u;
    asm("cvt.rna.tf32.f32 %0, %1;" : "=r"(u) : "f"(x));
    return __uint_as_float(u);
}

__device__ __forceinline__ void mma8(float& c0, float& c1, float& c2, float& c3,
                                     float a0, float a1, float a2, float a3,
                                     float b0, float b1) {
    asm volatile(
        "mma.sync.aligned.m16n8k8.row.col.f32.tf32.tf32.f32 "
        "{%0,%1,%2,%3}, {%4,%5,%6,%7}, {%8,%9}, {%0,%1,%2,%3};\n"
        : "+f"(c0), "+f"(c1), "+f"(c2), "+f"(c3)
        : "r"(__float_as_uint(a0)), "r"(__float_as_uint(a1)),
          "r"(__float_as_uint(a2)), "r"(__float_as_uint(a3)),
          "r"(__float_as_uint(b0)), "r"(__float_as_uint(b1)));
}

__device__ __forceinline__ uint32_t s2u(const void* p) {
    return (uint32_t)__cvta_generic_to_shared(p);
}
#define CPASYNC16(dst_u32, src_ptr) \
    asm volatile("cp.async.cg.shared.global [%0], [%1], 16;\n" \
                 :: "r"(dst_u32), "l"(src_ptr))

// ---------------------------------------------------------------------------
// Pipelined GEMM: C[M,N] = A[M,K] @ B[K,N], pre-rounded tf32 operands.
// Block 128x256, BK=64, 256 threads (8 warps, 2M x 4N, warp tile 64x64).
// 2-stage ring, distance-1 prefetch, ONE __syncthreads per k-iter (64 total).
// Hazard: barrier at iter t orders compute(t-1) [last reader of buf (t+1)&1]
// before prefetch(t+1) writes it; wait_group 0 + barrier publish buf t.
//   As[m][k] stride 68 -> (4m + k)%32 distinct over fragment lanes
//   Bs[k][n] stride 264 -> (8k + n)%32 distinct
// ---------------------------------------------------------------------------
#define BM 128
#define BN 256
#define BK 64
#define ASTRD 68
#define BSTRD 264
#define STG_FLOATS (BM * ASTRD + BK * BSTRD)            // 25600
#define GEMM_SMEM (2 * STG_FLOATS * 4)                  // 204800 B

__global__ __launch_bounds__(256, 1)
void gemm_tf32_pipe(const float* __restrict__ A, const float* __restrict__ B,
                    float* __restrict__ C, int M, int N, int K) {
    extern __shared__ float sm[];

    const int tid  = threadIdx.x;
    const int warp = tid >> 5, lane = tid & 31;
    const int tq = lane >> 2, tr = lane & 3;
    const int wm = (warp & 1) * 64;
    const int wn = (warp >> 1) * 64;
    const size_t bm = (size_t)blockIdx.x * BM;
    const size_t bn = (size_t)blockIdx.y * BN;

    float c[4][8][4];
    #pragma unroll
    for (int mi = 0; mi < 4; mi++)
        #pragma unroll
        for (int ni = 0; ni < 8; ni++)
            #pragma unroll
            for (int e = 0; e < 4; e++) c[mi][ni][e] = 0.f;

    const int NT = K / BK;   // 64

    // staging: A 128x64 = 2048 float4 (8/thr), B 64x256 = 4096 float4 (16/thr)
    auto stage = [&](int kt, int s) {
        float* sa = sm + s * STG_FLOATS;
        float* sb = sa + BM * ASTRD;
        #pragma unroll
        for (int i = 0; i < 8; i++) {
            int cdx = tid + 256 * i;
            int row = cdx >> 4, c4 = (cdx & 15) * 4;
            CPASYNC16(s2u(sa + row * ASTRD + c4),
                      A + (bm + row) * (size_t)K + kt + c4);
        }
        #pragma unroll
        for (int i = 0; i < 16; i++) {
            int cdx = tid + 256 * i;
            int row = cdx >> 6, c4 = (cdx & 63) * 4;
            CPASYNC16(s2u(sb + row * BSTRD + c4),
                      B + (size_t)(kt + row) * N + bn + c4);
        }
        asm volatile("cp.async.commit_group;\n");
    };

    stage(0, 0);

    for (int t = 0; t < NT; t++) {
        asm volatile("cp.async.wait_group 0;\n");   // own group(t) done
        __syncthreads();   // publish buf t; all warps past compute(t-1)
        if (t + 1 < NT) stage((t + 1) * BK, (t + 1) & 1);

        const float* sa = sm + (t & 1) * STG_FLOATS;
        const float* sb = sa + BM * ASTRD;

        #pragma unroll
        for (int kk = 0; kk < 8; kk++) {
            const int k0 = 8 * kk + tr;
            float a[4][4];
            #pragma unroll
            for (int mi = 0; mi < 4; mi++) {
                const int r0 = wm + 16 * mi + tq;
                a[mi][0] = sa[r0 * ASTRD + k0];
                a[mi][1] = sa[(r0 + 8) * ASTRD + k0];
                a[mi][2] = sa[r0 * ASTRD + k0 + 4];
                a[mi][3] = sa[(r0 + 8) * ASTRD + k0 + 4];
            }
            float b[8][2];
            #pragma unroll
            for (int ni = 0; ni < 8; ni++) {
                const int col = wn + 8 * ni + tq;
                b[ni][0] = sb[k0 * BSTRD + col];
                b[ni][1] = sb[(k0 + 4) * BSTRD + col];
            }
            #pragma unroll
            for (int mi = 0; mi < 4; mi++)
                #pragma unroll
                for (int ni = 0; ni < 8; ni++)
                    mma8(c[mi][ni][0], c[mi][ni][1], c[mi][ni][2], c[mi][ni][3],
                         a[mi][0], a[mi][1], a[mi][2], a[mi][3],
                         b[ni][0], b[ni][1]);
        }
    }

    #pragma unroll
    for (int mi = 0; mi < 4; mi++) {
        #pragma unroll
        for (int ni = 0; ni < 8; ni++) {
            size_t r  = bm + wm + 16 * mi + tq;
            size_t cc = bn + wn + 8 * ni + 2 * tr;
            *(float2*)(C + r * N + cc)       = make_float2(c[mi][ni][0], c[mi][ni][1]);
            *(float2*)(C + (r + 8) * N + cc) = make_float2(c[mi][ni][2], c[mi][ni][3]);
        }
    }
}

// ---------------------------------------------------------------------------
// prepass: elementwise tf32 rounding
// ---------------------------------------------------------------------------
__global__ void round_copy(const float* __restrict__ src, float* __restrict__ dst,
                           int n4) {
    int i = blockIdx.x * blockDim.x + threadIdx.x;
    if (i < n4) {
        float4 v = ((const float4*)src)[i];
        v.x = f2tf32(v.x); v.y = f2tf32(v.y); v.z = f2tf32(v.z); v.w = f2tf32(v.w);
        ((float4*)dst)[i] = v;
    }
}

// ---------------------------------------------------------------------------
// Per-(token, head) RMSNorm + RoPE (unchanged).
// ---------------------------------------------------------------------------
__global__ void norm_rope(const float* __restrict__ qw, const float* __restrict__ kw) {
    const int t = blockIdx.x;
    const int h = blockIdx.y;
    float* base = g_qkv + (size_t)t * QKV_N + h * HD;

    __shared__ float xs[HD];
    __shared__ float red[4];
    const int j = threadIdx.x;

    float x = base[j];
    xs[j] = x;
    float ss = x * x;
    #pragma unroll
    for (int o = 16; o > 0; o >>= 1) ss += __shfl_xor_sync(0xffffffffu, ss, o);
    if ((j & 31) == 0) red[j >> 5] = ss;
    __syncthreads();

    float scale = rsqrtf((red[0] + red[1] + red[2] + red[3]) * (1.0f / HD) + 1e-6f);
    const float* w = (h < NQH) ? qw : kw;

    if (j < 64) {
        float x1 = xs[j]      * scale * w[j];
        float x2 = xs[j + 64] * scale * w[j + 64];
        float invf = exp2f(-(float)j * (19.931568569324174f / 64.0f));
        float ang = (float)t * invf;
        float s, cth;
        sincosf(ang, &s, &cth);
        base[j]      = x1 * cth - x2 * s;
        base[j + 64] = x2 * cth + x1 * s;
    }
}

// ---------------------------------------------------------------------------
// GQA flash attention (R11, unchanged). CTA = (kv-head, 32-row q block).
// ---------------------------------------------------------------------------
#define QSTR 132
#define KSTR 132
#define VSTR 136
#define PSTR 68
#define QS_FLOATS (4 * 32 * QSTR)
#define KS_FLOATS (64 * KSTR)
#define VS_FLOATS (64 * VSTR)
#define PS_FLOATS (128 * PSTR)
#define ATTN_SMEM ((QS_FLOATS + KS_FLOATS + VS_FLOATS + PS_FLOATS) * 4)

__global__ __launch_bounds__(256, 1)
void flash_attn() {
    extern __shared__ float sm[];
    float* Qsp = sm;
    float (*Ks)[KSTR] = (float(*)[KSTR])(sm + QS_FLOATS);
    float (*Vs)[VSTR] = (float(*)[VSTR])(sm + QS_FLOATS + KS_FLOATS);
    float (*Ps)[PSTR] = (float(*)[PSTR])(sm + QS_FLOATS + KS_FLOATS + VS_FLOATS);

    const int kh = blockIdx.x;
    const int qb = blockIdx.y;
    const int tid = threadIdx.x;
    const int w = tid >> 5, lane = tid & 31;
    const int tq = lane >> 2, tr = lane & 3;
    const int hl = w >> 1;
    const int h  = 4 * kh + hl;
    const int wrow = (w & 1) * 16;
    const float scaling = 0.08838834764831845f;

    #pragma unroll
    for (int i = 0; i < 16; i++) {
        int f = tid + 256 * i;
        int head = f >> 10;
        int row  = (f >> 5) & 31;
        int c4   = (f & 31) * 4;
        float4 v = *(const float4*)(g_qkv + (size_t)(32 * qb + row) * QKV_N
                                    + (4 * kh + head) * HD + c4);
        v.x = f2tf32(v.x * scaling); v.y = f2tf32(v.y * scaling);
        v.z = f2tf32(v.z * scaling); v.w = f2tf32(v.w * scaling);
        *(float4*)&Qsp[head * 32 * QSTR + row * QSTR + c4] = v;
    }
    __syncthreads();

    float qf[16][4];
    const float* qbase = Qsp + hl * 32 * QSTR;
    #pragma unroll
    for (int kk = 0; kk < 16; kk++) {
        int r0 = wrow + tq, k0 = 8 * kk + tr;
        qf[kk][0] = qbase[r0 * QSTR + k0];
        qf[kk][1] = qbase[(r0 + 8) * QSTR + k0];
        qf[kk][2] = qbase[r0 * QSTR + k0 + 4];
        qf[kk][3] = qbase[(r0 + 8) * QSTR + k0 + 4];
    }

    float o[16][4];
    #pragma unroll
    for (int ni = 0; ni < 16; ni++)
        #pragma unroll
        for (int e = 0; e < 4; e++) o[ni][e] = 0.f;
    float m1 = -1e30f, m2 = -1e30f, l1 = 0.f, l2 = 0.f;

    const int r1 = 16 * w + tq, r2 = r1 + 8;
    const int rowg1 = 32 * qb + wrow + tq;
    const int rowg2 = rowg1 + 8;
    const int kb_last = (32 * qb + 31) >> 6;

    for (int kb = 0; kb <= kb_last; kb++) {
        __syncthreads();
        #pragma unroll
        for (int i = 0; i < 8; i++) {
            int f = tid + 256 * i;
            int row = f >> 5, c4 = (f & 31) * 4;
            const float* rp = g_qkv + (size_t)(64 * kb + row) * QKV_N;
            float4 kv = *(const float4*)(rp + 4096 + kh * HD + c4);
            kv.x = f2tf32(kv.x); kv.y = f2tf32(kv.y); kv.z = f2tf32(kv.z); kv.w = f2tf32(kv.w);
            *(float4*)&Ks[row][c4] = kv;
            float4 vv = *(const float4*)(rp + 5120 + kh * HD + c4);
            vv.x = f2tf32(vv.x); vv.y = f2tf32(vv.y); vv.z = f2tf32(vv.z); vv.w = f2tf32(vv.w);
            *(float4*)&Vs[row][c4] = vv;
        }
        __syncthreads();

        float s[8][4];
        #pragma unroll
        for (int ni = 0; ni < 8; ni++)
            #pragma unroll
            for (int e = 0; e < 4; e++) s[ni][e] = 0.f;

        #pragma unroll
        for (int kk = 0; kk < 16; kk++) {
            const int d0 = 8 * kk + tr;
            #pragma unroll
            for (int ni = 0; ni < 8; ni++) {
                float b0 = Ks[8 * ni + tq][d0];
                float b1 = Ks[8 * ni + tq][d0 + 4];
                mma8(s[ni][0], s[ni][1], s[ni][2], s[ni][3],
                     qf[kk][0], qf[kk][1], qf[kk][2], qf[kk][3], b0, b1);
            }
        }

        if (kb == kb_last) {
            #pragma unroll
            for (int ni = 0; ni < 8; ni++) {
                int c0g = 64 * kb + 8 * ni + 2 * tr;
                if (c0g     > rowg1) s[ni][0] = -1e30f;
                if (c0g + 1 > rowg1) s[ni][1] = -1e30f;
                if (c0g     > rowg2) s[ni][2] = -1e30f;
                if (c0g + 1 > rowg2) s[ni][3] = -1e30f;
            }
        }

        float tm1 = -1e30f, tm2 = -1e30f;
        #pragma unroll
        for (int ni = 0; ni < 8; ni++) {
            tm1 = fmaxf(tm1, fmaxf(s[ni][0], s[ni][1]));
            tm2 = fmaxf(tm2, fmaxf(s[ni][2], s[ni][3]));
        }
        tm1 = fmaxf(tm1, __shfl_xor_sync(0xffffffffu, tm1, 1));
        tm1 = fmaxf(tm1, __shfl_xor_sync(0xffffffffu, tm1, 2));
        tm2 = fmaxf(tm2, __shfl_xor_sync(0xffffffffu, tm2, 1));
        tm2 = fmaxf(tm2, __shfl_xor_sync(0xffffffffu, tm2, 2));

        float nm1 = fmaxf(m1, tm1), nm2 = fmaxf(m2, tm2);
        float a1 = __expf(m1 - nm1), a2 = __expf(m2 - nm2);

        float rs1 = 0.f, rs2 = 0.f;
        #pragma unroll
        for (int ni = 0; ni < 8; ni++) {
            int c0 = 8 * ni + 2 * tr;
            float p0 = __expf(s[ni][0] - nm1);
            float p1 = __expf(s[ni][1] - nm1);
            float p2 = __expf(s[ni][2] - nm2);
            float p3 = __expf(s[ni][3] - nm2);
            rs1 += p0 + p1; rs2 += p2 + p3;
            Ps[r1][c0]     = f2tf32(p0);
            Ps[r1][c0 + 1] = f2tf32(p1);
            Ps[r2][c0]     = f2tf32(p2);
            Ps[r2][c0 + 1] = f2tf32(p3);
        }
        rs1 += __shfl_xor_sync(0xffffffffu, rs1, 1);
        rs1 += __shfl_xor_sync(0xffffffffu, rs1, 2);
        rs2 += __shfl_xor_sync(0xffffffffu, rs2, 1);
        rs2 += __shfl_xor_sync(0xffffffffu, rs2, 2);

        l1 = l1 * a1 + rs1; l2 = l2 * a2 + rs2;
        m1 = nm1; m2 = nm2;

        #pragma unroll
        for (int ni = 0; ni < 16; ni++) {
            o[ni][0] *= a1; o[ni][1] *= a1;
            o[ni][2] *= a2; o[ni][3] *= a2;
        }

        __syncwarp();

        #pragma unroll
        for (int kp = 0; kp < 8; kp++) {
            float a0  = Ps[r1][8 * kp + tr];
            float a1f = Ps[r2][8 * kp + tr];
            float a2f = Ps[r1][8 * kp + tr + 4];
            float a3f = Ps[r2][8 * kp + tr + 4];
            #pragma unroll
            for (int ni = 0; ni < 16; ni++) {
                float b0 = Vs[8 * kp + tr][8 * ni + tq];
                float b1 = Vs[8 * kp + tr + 4][8 * ni + tq];
                mma8(o[ni][0], o[ni][1], o[ni][2], o[ni][3], a0, a1f, a2f, a3f, b0, b1);
            }
        }
    }

    const float inv1 = 1.0f / l1, inv2 = 1.0f / l2;
    #pragma unroll
    for (int ni = 0; ni < 16; ni++) {
        int d = 8 * ni + 2 * tr;
        *(float2*)(g_attn + (size_t)rowg1 * O_N + h * HD + d) =
            make_float2(f2tf32(o[ni][0] * inv1), f2tf32(o[ni][1] * inv1));
        *(float2*)(g_attn + (size_t)rowg2 * O_N + h * HD + d) =
            make_float2(f2tf32(o[ni][2] * inv2), f2tf32(o[ni][3] * inv2));
    }
}

// ---------------------------------------------------------------------------
extern "C" void kernel_launch(void* const* d_in, const int* in_sizes, int n_in,
                              void* d_out, int out_size) {
    const float* hidden = (const float*)d_in[1];
    const float* w_qkv  = (const float*)d_in[2];
    const float* qw     = (const float*)d_in[3];
    const float* kw     = (const float*)d_in[4];
    const float* w_o    = (const float*)d_in[5];
    float* out = (float*)d_out;

    void *qkv_p = nullptr, *attn_p = nullptr, *hidr_p = nullptr;
    void *wqkvr_p = nullptr, *wor_p = nullptr;
    cudaGetSymbolAddress(&qkv_p, g_qkv);
    cudaGetSymbolAddress(&attn_p, g_attn);
    cudaGetSymbolAddress(&hidr_p, g_hidr);
    cudaGetSymbolAddress(&wqkvr_p, g_wqkvr);
    cudaGetSymbolAddress(&wor_p, g_wor);

    static bool init_done = false;
    static cudaStream_t s_side = nullptr;
    static cudaEvent_t ev_fork = nullptr, ev_join = nullptr;
    if (!init_done) {
        cudaFuncSetAttribute(gemm_tf32_pipe,
                             cudaFuncAttributeMaxDynamicSharedMemorySize, GEMM_SMEM);
        cudaFuncSetAttribute(flash_attn,
                             cudaFuncAttributeMaxDynamicSharedMemorySize, ATTN_SMEM);
        cudaStreamCreateWithFlags(&s_side, cudaStreamNonBlocking);
        cudaEventCreateWithFlags(&ev_fork, cudaEventDisableTiming);
        cudaEventCreateWithFlags(&ev_join, cudaEventDisableTiming);
        init_done = true;
    }

    round_copy<<<(T_SEQ * HID / 4 + 255) / 256, 256>>>(
        hidden, (float*)hidr_p, T_SEQ * HID / 4);
    round_copy<<<(HID * QKV_N / 4 + 255) / 256, 256>>>(
        w_qkv, (float*)wqkvr_p, HID * QKV_N / 4);

    cudaEventRecord(ev_fork, 0);
    cudaStreamWaitEvent(s_side, ev_fork, 0);
    round_copy<<<(HID * O_N / 4 + 255) / 256, 256, 0, s_side>>>(
        w_o, (float*)wor_p, HID * O_N / 4);
    cudaEventRecord(ev_join, s_side);

    gemm_tf32_pipe<<<dim3(T_SEQ / BM, QKV_N / BN), 256, GEMM_SMEM>>>(
        (const float*)hidr_p, (const float*)wqkvr_p, (float*)qkv_p,
        T_SEQ, QKV_N, HID);

    norm_rope<<<dim3(T_SEQ, NQH + NKV), HD>>>(qw, kw);

    flash_attn<<<dim3(NKV, T_SEQ / 32), 256, ATTN_SMEM>>>();

    cudaStreamWaitEvent(0, ev_join, 0);

    gemm_tf32_pipe<<<dim3(T_SEQ / BM, O_N / BN), 256, GEMM_SMEM>>>(
        (const float*)attn_p, (const float*)wor_p, out,
        T_SEQ, O_N, HID);
}

// round 14
// speedup vs baseline: 1.0398x; 1.0398x over previous
#include <cuda_runtime.h>
#include <cstdint>
#include <math.h>

// ---------------------------------------------------------------------------
// Qwen3 attention block. Round 14: R10 GEMM restored (best, 594us) + RMSNorm/
// RoPE fused into the QKV GEMM epilogue (tile = 128 rows x 2 complete heads).
// norm_rope kernel and its qkv round-trip eliminated. Flash: R11 GQA.
// Side-stream w_o overlap kept.
// ---------------------------------------------------------------------------

#define T_SEQ 2048
#define HID   4096
#define NQH   32
#define NKV   8
#define HD    128
#define QKV_N 6144
#define O_N   4096

__device__ float g_qkv[(size_t)T_SEQ * QKV_N];
__device__ float g_attn[(size_t)T_SEQ * O_N];
__device__ float g_hidr[(size_t)T_SEQ * HID];
__device__ float g_wqkvr[(size_t)HID * QKV_N];
__device__ float g_wor[(size_t)HID * O_N];

__device__ __forceinline__ float f2tf32(float x) {
    uint32_t u;
    asm("cvt.rna.tf32.f32 %0, %1;" : "=r"(u) : "f"(x));
    return __uint_as_float(u);
}

__device__ __forceinline__ void mma8(float& c0, float& c1, float& c2, float& c3,
                                     float a0, float a1, float a2, float a3,
                                     float b0, float b1) {
    asm volatile(
        "mma.sync.aligned.m16n8k8.row.col.f32.tf32.tf32.f32 "
        "{%0,%1,%2,%3}, {%4,%5,%6,%7}, {%8,%9}, {%0,%1,%2,%3};\n"
        : "+f"(c0), "+f"(c1), "+f"(c2), "+f"(c3)
        : "r"(__float_as_uint(a0)), "r"(__float_as_uint(a1)),
          "r"(__float_as_uint(a2)), "r"(__float_as_uint(a3)),
          "r"(__float_as_uint(b0)), "r"(__float_as_uint(b1)));
}

__device__ __forceinline__ uint32_t s2u(const void* p) {
    return (uint32_t)__cvta_generic_to_shared(p);
}
#define CPASYNC16(dst_u32, src_ptr) \
    asm volatile("cp.async.cg.shared.global [%0], [%1], 16;\n" \
                 :: "r"(dst_u32), "l"(src_ptr))

// ---------------------------------------------------------------------------
// Pipelined GEMM (R10 mainloop): C[M,N] = A[M,K] @ B[K,N], tf32 operands.
// Block 128x256, BK=32, 256 threads, 4-stage cp.async ring, 1 barrier/iter.
// fuse=1 (QKV): epilogue stages tile in smem, applies RMSNorm+RoPE per head
// (tile holds exactly 2 complete heads), v-region plain copy.
// ---------------------------------------------------------------------------
#define BM 128
#define BN 256
#define BK 32
#define ASTRD 36
#define BSTRD 264
#define STG_FLOATS (BM * ASTRD + BK * BSTRD)            // 13056
#define GEMM_SMEM (4 * STG_FLOATS * 4)                  // 208896 B
#define CSTRD 264                                        // Cs stride (135KB)

__global__ __launch_bounds__(256, 1)
void gemm_tf32_pipe(const float* __restrict__ A, const float* __restrict__ B,
                    float* __restrict__ C, int M, int N, int K,
                    const float* __restrict__ qw, const float* __restrict__ kw,
                    int fuse) {
    extern __shared__ float sm[];

    const int tid  = threadIdx.x;
    const int warp = tid >> 5, lane = tid & 31;
    const int tq = lane >> 2, tr = lane & 3;
    const int wm = (warp & 1) * 64;
    const int wn = (warp >> 1) * 64;
    const size_t bm = (size_t)blockIdx.x * BM;
    const size_t bn = (size_t)blockIdx.y * BN;

    float c[4][8][4];
    #pragma unroll
    for (int mi = 0; mi < 4; mi++)
        #pragma unroll
        for (int ni = 0; ni < 8; ni++)
            #pragma unroll
            for (int e = 0; e < 4; e++) c[mi][ni][e] = 0.f;

    const int arow = tid >> 3, acol = (tid & 7) * 4;
    const int brow = tid >> 6, bcol = (tid & 63) * 4;
    const int NT = K / BK;

    auto stage = [&](int kt, int s) {
        float* sa = sm + s * STG_FLOATS;
        float* sb = sa + BM * ASTRD;
        #pragma unroll
        for (int i = 0; i < 4; i++)
            CPASYNC16(s2u(sa + (arow + 32 * i) * ASTRD + acol),
                      A + (bm + arow + 32 * i) * (size_t)K + kt + acol);
        #pragma unroll
        for (int i = 0; i < 8; i++)
            CPASYNC16(s2u(sb + (brow + 4 * i) * BSTRD + bcol),
                      B + (size_t)(kt + brow + 4 * i) * N + bn + bcol);
        asm volatile("cp.async.commit_group;\n");
    };

    stage(0, 0);
    stage(BK, 1);

    for (int t = 0; t < NT; t++) {
        if (t + 2 < NT) {
            stage((t + 2) * BK, (t + 2) & 3);
            asm volatile("cp.async.wait_group 2;\n");
        } else if (t + 1 < NT) {
            asm volatile("cp.async.wait_group 1;\n");
        } else {
            asm volatile("cp.async.wait_group 0;\n");
        }
        __syncthreads();

        const float* sa = sm + (t & 3) * STG_FLOATS;
        const float* sb = sa + BM * ASTRD;

        #pragma unroll
        for (int kk = 0; kk < 4; kk++) {
            const int k0 = 8 * kk + tr;
            float a[4][4];
            #pragma unroll
            for (int mi = 0; mi < 4; mi++) {
                const int r0 = wm + 16 * mi + tq;
                a[mi][0] = sa[r0 * ASTRD + k0];
                a[mi][1] = sa[(r0 + 8) * ASTRD + k0];
                a[mi][2] = sa[r0 * ASTRD + k0 + 4];
                a[mi][3] = sa[(r0 + 8) * ASTRD + k0 + 4];
            }
            float b[8][2];
            #pragma unroll
            for (int ni = 0; ni < 8; ni++) {
                const int col = wn + 8 * ni + tq;
                b[ni][0] = sb[k0 * BSTRD + col];
                b[ni][1] = sb[(k0 + 4) * BSTRD + col];
            }
            #pragma unroll
            for (int mi = 0; mi < 4; mi++)
                #pragma unroll
                for (int ni = 0; ni < 8; ni++)
                    mma8(c[mi][ni][0], c[mi][ni][1], c[mi][ni][2], c[mi][ni][3],
                         a[mi][0], a[mi][1], a[mi][2], a[mi][3],
                         b[ni][0], b[ni][1]);
        }
    }

    if (!fuse) {
        #pragma unroll
        for (int mi = 0; mi < 4; mi++) {
            #pragma unroll
            for (int ni = 0; ni < 8; ni++) {
                size_t r  = bm + wm + 16 * mi + tq;
                size_t cc = bn + wn + 8 * ni + 2 * tr;
                *(float2*)(C + r * N + cc)       = make_float2(c[mi][ni][0], c[mi][ni][1]);
                *(float2*)(C + (r + 8) * N + cc) = make_float2(c[mi][ni][2], c[mi][ni][3]);
            }
        }
        return;
    }

    // ---- fused epilogue: stage tile into smem, RMSNorm+RoPE per head ----
    __syncthreads();                 // all warps done reading ring buffers
    float (*Cs)[CSTRD] = (float(*)[CSTRD])sm;
    #pragma unroll
    for (int mi = 0; mi < 4; mi++) {
        #pragma unroll
        for (int ni = 0; ni < 8; ni++) {
            int r  = wm + 16 * mi + tq;
            int cc = wn + 8 * ni + 2 * tr;
            *(float2*)&Cs[r][cc]     = make_float2(c[mi][ni][0], c[mi][ni][1]);
            *(float2*)&Cs[r + 8][cc] = make_float2(c[mi][ni][2], c[mi][ni][3]);
        }
    }
    __syncthreads();

    const int gh0 = (int)(bn >> 7);            // first head in this tile
    for (int it = 0; it < 32; it++) {
        const int p   = warp * 32 + it;        // pair id 0..255
        const int row = p & 127;
        const int hl  = p >> 7;                // 0 or 1
        const int gh  = gh0 + hl;              // global head index (0..47)
        const float* src = &Cs[row][hl * HD];
        float* dst = C + (bm + row) * (size_t)N + bn + hl * HD;

        float v0 = src[lane];
        float v1 = src[lane + 32];
        float v2 = src[lane + 64];
        float v3 = src[lane + 96];

        if (gh >= NQH + NKV) {                 // v region: plain store
            dst[lane]      = v0;
            dst[lane + 32] = v1;
            dst[lane + 64] = v2;
            dst[lane + 96] = v3;
        } else {
            float ss = v0 * v0 + v1 * v1 + v2 * v2 + v3 * v3;
            #pragma unroll
            for (int o = 16; o > 0; o >>= 1) ss += __shfl_xor_sync(0xffffffffu, ss, o);
            float scale = rsqrtf(ss * (1.0f / HD) + 1e-6f);
            const float* wv = (gh < NQH) ? qw : kw;
            // rope pairs: (lane, lane+64) and (lane+32, lane+96)
            float x1a = v0 * scale * wv[lane];
            float x2a = v2 * scale * wv[lane + 64];
            float x1b = v1 * scale * wv[lane + 32];
            float x2b = v3 * scale * wv[lane + 96];
            float tpos = (float)(bm + row);
            float ia = exp2f(-(float)lane        * (19.931568569324174f / 64.0f));
            float ib = exp2f(-(float)(lane + 32) * (19.931568569324174f / 64.0f));
            float sa_, ca_, sb_, cb_;
            sincosf(tpos * ia, &sa_, &ca_);
            sincosf(tpos * ib, &sb_, &cb_);
            dst[lane]      = x1a * ca_ - x2a * sa_;
            dst[lane + 64] = x2a * ca_ + x1a * sa_;
            dst[lane + 32] = x1b * cb_ - x2b * sb_;
            dst[lane + 96] = x2b * cb_ + x1b * sb_;
        }
    }
}

// ---------------------------------------------------------------------------
// prepass: elementwise tf32 rounding
// ---------------------------------------------------------------------------
__global__ void round_copy(const float* __restrict__ src, float* __restrict__ dst,
                           int n4) {
    int i = blockIdx.x * blockDim.x + threadIdx.x;
    if (i < n4) {
        float4 v = ((const float4*)src)[i];
        v.x = f2tf32(v.x); v.y = f2tf32(v.y); v.z = f2tf32(v.z); v.w = f2tf32(v.w);
        ((float4*)dst)[i] = v;
    }
}

// ---------------------------------------------------------------------------
// GQA flash attention (R11, unchanged). CTA = (kv-head, 32-row q block).
// ---------------------------------------------------------------------------
#define QSTR 132
#define KSTR 132
#define VSTR 136
#define PSTR 68
#define QS_FLOATS (4 * 32 * QSTR)
#define KS_FLOATS (64 * KSTR)
#define VS_FLOATS (64 * VSTR)
#define PS_FLOATS (128 * PSTR)
#define ATTN_SMEM ((QS_FLOATS + KS_FLOATS + VS_FLOATS + PS_FLOATS) * 4)

__global__ __launch_bounds__(256, 1)
void flash_attn() {
    extern __shared__ float sm[];
    float* Qsp = sm;
    float (*Ks)[KSTR] = (float(*)[KSTR])(sm + QS_FLOATS);
    float (*Vs)[VSTR] = (float(*)[VSTR])(sm + QS_FLOATS + KS_FLOATS);
    float (*Ps)[PSTR] = (float(*)[PSTR])(sm + QS_FLOATS + KS_FLOATS + VS_FLOATS);

    const int kh = blockIdx.x;
    const int qb = blockIdx.y;
    const int tid = threadIdx.x;
    const int w = tid >> 5, lane = tid & 31;
    const int tq = lane >> 2, tr = lane & 3;
    const int hl = w >> 1;
    const int h  = 4 * kh + hl;
    const int wrow = (w & 1) * 16;
    const float scaling = 0.08838834764831845f;

    #pragma unroll
    for (int i = 0; i < 16; i++) {
        int f = tid + 256 * i;
        int head = f >> 10;
        int row  = (f >> 5) & 31;
        int c4   = (f & 31) * 4;
        float4 v = *(const float4*)(g_qkv + (size_t)(32 * qb + row) * QKV_N
                                    + (4 * kh + head) * HD + c4);
        v.x = f2tf32(v.x * scaling); v.y = f2tf32(v.y * scaling);
        v.z = f2tf32(v.z * scaling); v.w = f2tf32(v.w * scaling);
        *(float4*)&Qsp[head * 32 * QSTR + row * QSTR + c4] = v;
    }
    __syncthreads();

    float qf[16][4];
    const float* qbase = Qsp + hl * 32 * QSTR;
    #pragma unroll
    for (int kk = 0; kk < 16; kk++) {
        int r0 = wrow + tq, k0 = 8 * kk + tr;
        qf[kk][0] = qbase[r0 * QSTR + k0];
        qf[kk][1] = qbase[(r0 + 8) * QSTR + k0];
        qf[kk][2] = qbase[r0 * QSTR + k0 + 4];
        qf[kk][3] = qbase[(r0 + 8) * QSTR + k0 + 4];
    }

    float o[16][4];
    #pragma unroll
    for (int ni = 0; ni < 16; ni++)
        #pragma unroll
        for (int e = 0; e < 4; e++) o[ni][e] = 0.f;
    float m1 = -1e30f, m2 = -1e30f, l1 = 0.f, l2 = 0.f;

    const int r1 = 16 * w + tq, r2 = r1 + 8;
    const int rowg1 = 32 * qb + wrow + tq;
    const int rowg2 = rowg1 + 8;
    const int kb_last = (32 * qb + 31) >> 6;

    for (int kb = 0; kb <= kb_last; kb++) {
        __syncthreads();
        #pragma unroll
        for (int i = 0; i < 8; i++) {
            int f = tid + 256 * i;
            int row = f >> 5, c4 = (f & 31) * 4;
            const float* rp = g_qkv + (size_t)(64 * kb + row) * QKV_N;
            float4 kv = *(const float4*)(rp + 4096 + kh * HD + c4);
            kv.x = f2tf32(kv.x); kv.y = f2tf32(kv.y); kv.z = f2tf32(kv.z); kv.w = f2tf32(kv.w);
            *(float4*)&Ks[row][c4] = kv;
            float4 vv = *(const float4*)(rp + 5120 + kh * HD + c4);
            vv.x = f2tf32(vv.x); vv.y = f2tf32(vv.y); vv.z = f2tf32(vv.z); vv.w = f2tf32(vv.w);
            *(float4*)&Vs[row][c4] = vv;
        }
        __syncthreads();

        float s[8][4];
        #pragma unroll
        for (int ni = 0; ni < 8; ni++)
            #pragma unroll
            for (int e = 0; e < 4; e++) s[ni][e] = 0.f;

        #pragma unroll
        for (int kk = 0; kk < 16; kk++) {
            const int d0 = 8 * kk + tr;
            #pragma unroll
            for (int ni = 0; ni < 8; ni++) {
                float b0 = Ks[8 * ni + tq][d0];
                float b1 = Ks[8 * ni + tq][d0 + 4];
                mma8(s[ni][0], s[ni][1], s[ni][2], s[ni][3],
                     qf[kk][0], qf[kk][1], qf[kk][2], qf[kk][3], b0, b1);
            }
        }

        if (kb == kb_last) {
            #pragma unroll
            for (int ni = 0; ni < 8; ni++) {
                int c0g = 64 * kb + 8 * ni + 2 * tr;
                if (c0g     > rowg1) s[ni][0] = -1e30f;
                if (c0g + 1 > rowg1) s[ni][1] = -1e30f;
                if (c0g     > rowg2) s[ni][2] = -1e30f;
                if (c0g + 1 > rowg2) s[ni][3] = -1e30f;
            }
        }

        float tm1 = -1e30f, tm2 = -1e30f;
        #pragma unroll
        for (int ni = 0; ni < 8; ni++) {
            tm1 = fmaxf(tm1, fmaxf(s[ni][0], s[ni][1]));
            tm2 = fmaxf(tm2, fmaxf(s[ni][2], s[ni][3]));
        }
        tm1 = fmaxf(tm1, __shfl_xor_sync(0xffffffffu, tm1, 1));
        tm1 = fmaxf(tm1, __shfl_xor_sync(0xffffffffu, tm1, 2));
        tm2 = fmaxf(tm2, __shfl_xor_sync(0xffffffffu, tm2, 1));
        tm2 = fmaxf(tm2, __shfl_xor_sync(0xffffffffu, tm2, 2));

        float nm1 = fmaxf(m1, tm1), nm2 = fmaxf(m2, tm2);
        float a1 = __expf(m1 - nm1), a2 = __expf(m2 - nm2);

        float rs1 = 0.f, rs2 = 0.f;
        #pragma unroll
        for (int ni = 0; ni < 8; ni++) {
            int c0 = 8 * ni + 2 * tr;
            float p0 = __expf(s[ni][0] - nm1);
            float p1 = __expf(s[ni][1] - nm1);
            float p2 = __expf(s[ni][2] - nm2);
            float p3 = __expf(s[ni][3] - nm2);
            rs1 += p0 + p1; rs2 += p2 + p3;
            Ps[r1][c0]     = f2tf32(p0);
            Ps[r1][c0 + 1] = f2tf32(p1);
            Ps[r2][c0]     = f2tf32(p2);
            Ps[r2][c0 + 1] = f2tf32(p3);
        }
        rs1 += __shfl_xor_sync(0xffffffffu, rs1, 1);
        rs1 += __shfl_xor_sync(0xffffffffu, rs1, 2);
        rs2 += __shfl_xor_sync(0xffffffffu, rs2, 1);
        rs2 += __shfl_xor_sync(0xffffffffu, rs2, 2);

        l1 = l1 * a1 + rs1; l2 = l2 * a2 + rs2;
        m1 = nm1; m2 = nm2;

        #pragma unroll
        for (int ni = 0; ni < 16; ni++) {
            o[ni][0] *= a1; o[ni][1] *= a1;
            o[ni][2] *= a2; o[ni][3] *= a2;
        }

        __syncwarp();

        #pragma unroll
        for (int kp = 0; kp < 8; kp++) {
            float a0  = Ps[r1][8 * kp + tr];
            float a1f = Ps[r2][8 * kp + tr];
            float a2f = Ps[r1][8 * kp + tr + 4];
            float a3f = Ps[r2][8 * kp + tr + 4];
            #pragma unroll
            for (int ni = 0; ni < 16; ni++) {
                float b0 = Vs[8 * kp + tr][8 * ni + tq];
                float b1 = Vs[8 * kp + tr + 4][8 * ni + tq];
                mma8(o[ni][0], o[ni][1], o[ni][2], o[ni][3], a0, a1f, a2f, a3f, b0, b1);
            }
        }
    }

    const float inv1 = 1.0f / l1, inv2 = 1.0f / l2;
    #pragma unroll
    for (int ni = 0; ni < 16; ni++) {
        int d = 8 * ni + 2 * tr;
        *(float2*)(g_attn + (size_t)rowg1 * O_N + h * HD + d) =
            make_float2(f2tf32(o[ni][0] * inv1), f2tf32(o[ni][1] * inv1));
        *(float2*)(g_attn + (size_t)rowg2 * O_N + h * HD + d) =
            make_float2(f2tf32(o[ni][2] * inv2), f2tf32(o[ni][3] * inv2));
    }
}

// ---------------------------------------------------------------------------
extern "C" void kernel_launch(void* const* d_in, const int* in_sizes, int n_in,
                              void* d_out, int out_size) {
    const float* hidden = (const float*)d_in[1];
    const float* w_qkv  = (const float*)d_in[2];
    const float* qw     = (const float*)d_in[3];
    const float* kw     = (const float*)d_in[4];
    const float* w_o    = (const float*)d_in[5];
    float* out = (float*)d_out;

    void *qkv_p = nullptr, *attn_p = nullptr, *hidr_p = nullptr;
    void *wqkvr_p = nullptr, *wor_p = nullptr;
    cudaGetSymbolAddress(&qkv_p, g_qkv);
    cudaGetSymbolAddress(&attn_p, g_attn);
    cudaGetSymbolAddress(&hidr_p, g_hidr);
    cudaGetSymbolAddress(&wqkvr_p, g_wqkvr);
    cudaGetSymbolAddress(&wor_p, g_wor);

    static bool init_done = false;
    static cudaStream_t s_side = nullptr;
    static cudaEvent_t ev_fork = nullptr, ev_join = nullptr;
    if (!init_done) {
        cudaFuncSetAttribute(gemm_tf32_pipe,
                             cudaFuncAttributeMaxDynamicSharedMemorySize, GEMM_SMEM);
        cudaFuncSetAttribute(flash_attn,
                             cudaFuncAttributeMaxDynamicSharedMemorySize, ATTN_SMEM);
        cudaStreamCreateWithFlags(&s_side, cudaStreamNonBlocking);
        cudaEventCreateWithFlags(&ev_fork, cudaEventDisableTiming);
        cudaEventCreateWithFlags(&ev_join, cudaEventDisableTiming);
        init_done = true;
    }

    round_copy<<<(T_SEQ * HID / 4 + 255) / 256, 256>>>(
        hidden, (float*)hidr_p, T_SEQ * HID / 4);
    round_copy<<<(HID * QKV_N / 4 + 255) / 256, 256>>>(
        w_qkv, (float*)wqkvr_p, HID * QKV_N / 4);

    cudaEventRecord(ev_fork, 0);
    cudaStreamWaitEvent(s_side, ev_fork, 0);
    round_copy<<<(HID * O_N / 4 + 255) / 256, 256, 0, s_side>>>(
        w_o, (float*)wor_p, HID * O_N / 4);
    cudaEventRecord(ev_join, s_side);

    // QKV GEMM with fused RMSNorm+RoPE epilogue
    gemm_tf32_pipe<<<dim3(T_SEQ / BM, QKV_N / BN), 256, GEMM_SMEM>>>(
        (const float*)hidr_p, (const float*)wqkvr_p, (float*)qkv_p,
        T_SEQ, QKV_N, HID, qw, kw, 1);

    flash_attn<<<dim3(NKV, T_SEQ / 32), 256, ATTN_SMEM>>>();

    cudaStreamWaitEvent(0, ev_join, 0);

    gemm_tf32_pipe<<<dim3(T_SEQ / BM, O_N / BN), 256, GEMM_SMEM>>>(
        (const float*)attn_p, (const float*)wor_p, out,
        T_SEQ, O_N, HID, nullptr, nullptr, 0);
}

// round 15
// speedup vs baseline: 1.0847x; 1.0432x over previous
#include <cuda_runtime.h>
#include <cstdint>
#include <math.h>

// ---------------------------------------------------------------------------
// Qwen3 attention block. Round 15: flash LPT scheduling.
//   - flash CTA qb reversed (qb = 63 - blockIdx.y): heaviest CTAs (32 KV
//     iters) launch first, 1-iter CTAs fill the tail -> makespan ~= ideal.
//   - w_o side-stream forked before w_qkv prepass (overlaps it too).
//   - GEMM + fused RMSNorm/RoPE epilogue (R14 WIN) unchanged.
// ---------------------------------------------------------------------------

#define T_SEQ 2048
#define HID   4096
#define NQH   32
#define NKV   8
#define HD    128
#define QKV_N 6144
#define O_N   4096

__device__ float g_qkv[(size_t)T_SEQ * QKV_N];
__device__ float g_attn[(size_t)T_SEQ * O_N];
__device__ float g_hidr[(size_t)T_SEQ * HID];
__device__ float g_wqkvr[(size_t)HID * QKV_N];
__device__ float g_wor[(size_t)HID * O_N];

__device__ __forceinline__ float f2tf32(float x) {
    uint32_t u;
    asm("cvt.rna.tf32.f32 %0, %1;" : "=r"(u) : "f"(x));
    return __uint_as_float(u);
}

__device__ __forceinline__ void mma8(float& c0, float& c1, float& c2, float& c3,
                                     float a0, float a1, float a2, float a3,
                                     float b0, float b1) {
    asm volatile(
        "mma.sync.aligned.m16n8k8.row.col.f32.tf32.tf32.f32 "
        "{%0,%1,%2,%3}, {%4,%5,%6,%7}, {%8,%9}, {%0,%1,%2,%3};\n"
        : "+f"(c0), "+f"(c1), "+f"(c2), "+f"(c3)
        : "r"(__float_as_uint(a0)), "r"(__float_as_uint(a1)),
          "r"(__float_as_uint(a2)), "r"(__float_as_uint(a3)),
          "r"(__float_as_uint(b0)), "r"(__float_as_uint(b1)));
}

__device__ __forceinline__ uint32_t s2u(const void* p) {
    return (uint32_t)__cvta_generic_to_shared(p);
}
#define CPASYNC16(dst_u32, src_ptr) \
    asm volatile("cp.async.cg.shared.global [%0], [%1], 16;\n" \
                 :: "r"(dst_u32), "l"(src_ptr))

// ---------------------------------------------------------------------------
// Pipelined GEMM (R10 mainloop): C[M,N] = A[M,K] @ B[K,N], tf32 operands.
// Block 128x256, BK=32, 256 threads, 4-stage cp.async ring, 1 barrier/iter.
// fuse=1 (QKV): epilogue stages tile in smem, applies RMSNorm+RoPE per head.
// ---------------------------------------------------------------------------
#define BM 128
#define BN 256
#define BK 32
#define ASTRD 36
#define BSTRD 264
#define STG_FLOATS (BM * ASTRD + BK * BSTRD)            // 13056
#define GEMM_SMEM (4 * STG_FLOATS * 4)                  // 208896 B
#define CSTRD 264

__global__ __launch_bounds__(256, 1)
void gemm_tf32_pipe(const float* __restrict__ A, const float* __restrict__ B,
                    float* __restrict__ C, int M, int N, int K,
                    const float* __restrict__ qw, const float* __restrict__ kw,
                    int fuse) {
    extern __shared__ float sm[];

    const int tid  = threadIdx.x;
    const int warp = tid >> 5, lane = tid & 31;
    const int tq = lane >> 2, tr = lane & 3;
    const int wm = (warp & 1) * 64;
    const int wn = (warp >> 1) * 64;
    const size_t bm = (size_t)blockIdx.x * BM;
    const size_t bn = (size_t)blockIdx.y * BN;

    float c[4][8][4];
    #pragma unroll
    for (int mi = 0; mi < 4; mi++)
        #pragma unroll
        for (int ni = 0; ni < 8; ni++)
            #pragma unroll
            for (int e = 0; e < 4; e++) c[mi][ni][e] = 0.f;

    const int arow = tid >> 3, acol = (tid & 7) * 4;
    const int brow = tid >> 6, bcol = (tid & 63) * 4;
    const int NT = K / BK;

    auto stage = [&](int kt, int s) {
        float* sa = sm + s * STG_FLOATS;
        float* sb = sa + BM * ASTRD;
        #pragma unroll
        for (int i = 0; i < 4; i++)
            CPASYNC16(s2u(sa + (arow + 32 * i) * ASTRD + acol),
                      A + (bm + arow + 32 * i) * (size_t)K + kt + acol);
        #pragma unroll
        for (int i = 0; i < 8; i++)
            CPASYNC16(s2u(sb + (brow + 4 * i) * BSTRD + bcol),
                      B + (size_t)(kt + brow + 4 * i) * N + bn + bcol);
        asm volatile("cp.async.commit_group;\n");
    };

    stage(0, 0);
    stage(BK, 1);

    for (int t = 0; t < NT; t++) {
        if (t + 2 < NT) {
            stage((t + 2) * BK, (t + 2) & 3);
            asm volatile("cp.async.wait_group 2;\n");
        } else if (t + 1 < NT) {
            asm volatile("cp.async.wait_group 1;\n");
        } else {
            asm volatile("cp.async.wait_group 0;\n");
        }
        __syncthreads();

        const float* sa = sm + (t & 3) * STG_FLOATS;
        const float* sb = sa + BM * ASTRD;

        #pragma unroll
        for (int kk = 0; kk < 4; kk++) {
            const int k0 = 8 * kk + tr;
            float a[4][4];
            #pragma unroll
            for (int mi = 0; mi < 4; mi++) {
                const int r0 = wm + 16 * mi + tq;
                a[mi][0] = sa[r0 * ASTRD + k0];
                a[mi][1] = sa[(r0 + 8) * ASTRD + k0];
                a[mi][2] = sa[r0 * ASTRD + k0 + 4];
                a[mi][3] = sa[(r0 + 8) * ASTRD + k0 + 4];
            }
            float b[8][2];
            #pragma unroll
            for (int ni = 0; ni < 8; ni++) {
                const int col = wn + 8 * ni + tq;
                b[ni][0] = sb[k0 * BSTRD + col];
                b[ni][1] = sb[(k0 + 4) * BSTRD + col];
            }
            #pragma unroll
            for (int mi = 0; mi < 4; mi++)
                #pragma unroll
                for (int ni = 0; ni < 8; ni++)
                    mma8(c[mi][ni][0], c[mi][ni][1], c[mi][ni][2], c[mi][ni][3],
                         a[mi][0], a[mi][1], a[mi][2], a[mi][3],
                         b[ni][0], b[ni][1]);
        }
    }

    if (!fuse) {
        #pragma unroll
        for (int mi = 0; mi < 4; mi++) {
            #pragma unroll
            for (int ni = 0; ni < 8; ni++) {
                size_t r  = bm + wm + 16 * mi + tq;
                size_t cc = bn + wn + 8 * ni + 2 * tr;
                *(float2*)(C + r * N + cc)       = make_float2(c[mi][ni][0], c[mi][ni][1]);
                *(float2*)(C + (r + 8) * N + cc) = make_float2(c[mi][ni][2], c[mi][ni][3]);
            }
        }
        return;
    }

    // ---- fused epilogue: stage tile into smem, RMSNorm+RoPE per head ----
    __syncthreads();
    float (*Cs)[CSTRD] = (float(*)[CSTRD])sm;
    #pragma unroll
    for (int mi = 0; mi < 4; mi++) {
        #pragma unroll
        for (int ni = 0; ni < 8; ni++) {
            int r  = wm + 16 * mi + tq;
            int cc = wn + 8 * ni + 2 * tr;
            *(float2*)&Cs[r][cc]     = make_float2(c[mi][ni][0], c[mi][ni][1]);
            *(float2*)&Cs[r + 8][cc] = make_float2(c[mi][ni][2], c[mi][ni][3]);
        }
    }
    __syncthreads();

    const int gh0 = (int)(bn >> 7);
    for (int it = 0; it < 32; it++) {
        const int p   = warp * 32 + it;
        const int row = p & 127;
        const int hl  = p >> 7;
        const int gh  = gh0 + hl;
        const float* src = &Cs[row][hl * HD];
        float* dst = C + (bm + row) * (size_t)N + bn + hl * HD;

        float v0 = src[lane];
        float v1 = src[lane + 32];
        float v2 = src[lane + 64];
        float v3 = src[lane + 96];

        if (gh >= NQH + NKV) {
            dst[lane]      = v0;
            dst[lane + 32] = v1;
            dst[lane + 64] = v2;
            dst[lane + 96] = v3;
        } else {
            float ss = v0 * v0 + v1 * v1 + v2 * v2 + v3 * v3;
            #pragma unroll
            for (int o = 16; o > 0; o >>= 1) ss += __shfl_xor_sync(0xffffffffu, ss, o);
            float scale = rsqrtf(ss * (1.0f / HD) + 1e-6f);
            const float* wv = (gh < NQH) ? qw : kw;
            float x1a = v0 * scale * wv[lane];
            float x2a = v2 * scale * wv[lane + 64];
            float x1b = v1 * scale * wv[lane + 32];
            float x2b = v3 * scale * wv[lane + 96];
            float tpos = (float)(bm + row);
            float ia = exp2f(-(float)lane        * (19.931568569324174f / 64.0f));
            float ib = exp2f(-(float)(lane + 32) * (19.931568569324174f / 64.0f));
            float sa_, ca_, sb_, cb_;
            sincosf(tpos * ia, &sa_, &ca_);
            sincosf(tpos * ib, &sb_, &cb_);
            dst[lane]      = x1a * ca_ - x2a * sa_;
            dst[lane + 64] = x2a * ca_ + x1a * sa_;
            dst[lane + 32] = x1b * cb_ - x2b * sb_;
            dst[lane + 96] = x2b * cb_ + x1b * sb_;
        }
    }
}

// ---------------------------------------------------------------------------
// prepass: elementwise tf32 rounding
// ---------------------------------------------------------------------------
__global__ void round_copy(const float* __restrict__ src, float* __restrict__ dst,
                           int n4) {
    int i = blockIdx.x * blockDim.x + threadIdx.x;
    if (i < n4) {
        float4 v = ((const float4*)src)[i];
        v.x = f2tf32(v.x); v.y = f2tf32(v.y); v.z = f2tf32(v.z); v.w = f2tf32(v.w);
        ((float4*)dst)[i] = v;
    }
}

// ---------------------------------------------------------------------------
// GQA flash attention. CTA = (kv-head, 32-row q block), HEAVY-FIRST: the
// kb-loop length is qb/2+1, so qb is reversed vs blockIdx.y to start the
// longest CTAs in wave 1 (LPT schedule).
// ---------------------------------------------------------------------------
#define QSTR 132
#define KSTR 132
#define VSTR 136
#define PSTR 68
#define QS_FLOATS (4 * 32 * QSTR)
#define KS_FLOATS (64 * KSTR)
#define VS_FLOATS (64 * VSTR)
#define PS_FLOATS (128 * PSTR)
#define ATTN_SMEM ((QS_FLOATS + KS_FLOATS + VS_FLOATS + PS_FLOATS) * 4)

__global__ __launch_bounds__(256, 1)
void flash_attn() {
    extern __shared__ float sm[];
    float* Qsp = sm;
    float (*Ks)[KSTR] = (float(*)[KSTR])(sm + QS_FLOATS);
    float (*Vs)[VSTR] = (float(*)[VSTR])(sm + QS_FLOATS + KS_FLOATS);
    float (*Ps)[PSTR] = (float(*)[PSTR])(sm + QS_FLOATS + KS_FLOATS + VS_FLOATS);

    const int kh = blockIdx.x;
    const int qb = (T_SEQ / 32 - 1) - blockIdx.y;   // heavy-first (LPT)
    const int tid = threadIdx.x;
    const int w = tid >> 5, lane = tid & 31;
    const int tq = lane >> 2, tr = lane & 3;
    const int hl = w >> 1;
    const int h  = 4 * kh + hl;
    const int wrow = (w & 1) * 16;
    const float scaling = 0.08838834764831845f;

    #pragma unroll
    for (int i = 0; i < 16; i++) {
        int f = tid + 256 * i;
        int head = f >> 10;
        int row  = (f >> 5) & 31;
        int c4   = (f & 31) * 4;
        float4 v = *(const float4*)(g_qkv + (size_t)(32 * qb + row) * QKV_N
                                    + (4 * kh + head) * HD + c4);
        v.x = f2tf32(v.x * scaling); v.y = f2tf32(v.y * scaling);
        v.z = f2tf32(v.z * scaling); v.w = f2tf32(v.w * scaling);
        *(float4*)&Qsp[head * 32 * QSTR + row * QSTR + c4] = v;
    }
    __syncthreads();

    float qf[16][4];
    const float* qbase = Qsp + hl * 32 * QSTR;
    #pragma unroll
    for (int kk = 0; kk < 16; kk++) {
        int r0 = wrow + tq, k0 = 8 * kk + tr;
        qf[kk][0] = qbase[r0 * QSTR + k0];
        qf[kk][1] = qbase[(r0 + 8) * QSTR + k0];
        qf[kk][2] = qbase[r0 * QSTR + k0 + 4];
        qf[kk][3] = qbase[(r0 + 8) * QSTR + k0 + 4];
    }

    float o[16][4];
    #pragma unroll
    for (int ni = 0; ni < 16; ni++)
        #pragma unroll
        for (int e = 0; e < 4; e++) o[ni][e] = 0.f;
    float m1 = -1e30f, m2 = -1e30f, l1 = 0.f, l2 = 0.f;

    const int r1 = 16 * w + tq, r2 = r1 + 8;
    const int rowg1 = 32 * qb + wrow + tq;
    const int rowg2 = rowg1 + 8;
    const int kb_last = (32 * qb + 31) >> 6;

    for (int kb = 0; kb <= kb_last; kb++) {
        __syncthreads();
        #pragma unroll
        for (int i = 0; i < 8; i++) {
            int f = tid + 256 * i;
            int row = f >> 5, c4 = (f & 31) * 4;
            const float* rp = g_qkv + (size_t)(64 * kb + row) * QKV_N;
            float4 kv = *(const float4*)(rp + 4096 + kh * HD + c4);
            kv.x = f2tf32(kv.x); kv.y = f2tf32(kv.y); kv.z = f2tf32(kv.z); kv.w = f2tf32(kv.w);
            *(float4*)&Ks[row][c4] = kv;
            float4 vv = *(const float4*)(rp + 5120 + kh * HD + c4);
            vv.x = f2tf32(vv.x); vv.y = f2tf32(vv.y); vv.z = f2tf32(vv.z); vv.w = f2tf32(vv.w);
            *(float4*)&Vs[row][c4] = vv;
        }
        __syncthreads();

        float s[8][4];
        #pragma unroll
        for (int ni = 0; ni < 8; ni++)
            #pragma unroll
            for (int e = 0; e < 4; e++) s[ni][e] = 0.f;

        #pragma unroll
        for (int kk = 0; kk < 16; kk++) {
            const int d0 = 8 * kk + tr;
            #pragma unroll
            for (int ni = 0; ni < 8; ni++) {
                float b0 = Ks[8 * ni + tq][d0];
                float b1 = Ks[8 * ni + tq][d0 + 4];
                mma8(s[ni][0], s[ni][1], s[ni][2], s[ni][3],
                     qf[kk][0], qf[kk][1], qf[kk][2], qf[kk][3], b0, b1);
            }
        }

        if (kb == kb_last) {
            #pragma unroll
            for (int ni = 0; ni < 8; ni++) {
                int c0g = 64 * kb + 8 * ni + 2 * tr;
                if (c0g     > rowg1) s[ni][0] = -1e30f;
                if (c0g + 1 > rowg1) s[ni][1] = -1e30f;
                if (c0g     > rowg2) s[ni][2] = -1e30f;
                if (c0g + 1 > rowg2) s[ni][3] = -1e30f;
            }
        }

        float tm1 = -1e30f, tm2 = -1e30f;
        #pragma unroll
        for (int ni = 0; ni < 8; ni++) {
            tm1 = fmaxf(tm1, fmaxf(s[ni][0], s[ni][1]));
            tm2 = fmaxf(tm2, fmaxf(s[ni][2], s[ni][3]));
        }
        tm1 = fmaxf(tm1, __shfl_xor_sync(0xffffffffu, tm1, 1));
        tm1 = fmaxf(tm1, __shfl_xor_sync(0xffffffffu, tm1, 2));
        tm2 = fmaxf(tm2, __shfl_xor_sync(0xffffffffu, tm2, 1));
        tm2 = fmaxf(tm2, __shfl_xor_sync(0xffffffffu, tm2, 2));

        float nm1 = fmaxf(m1, tm1), nm2 = fmaxf(m2, tm2);
        float a1 = __expf(m1 - nm1), a2 = __expf(m2 - nm2);

        float rs1 = 0.f, rs2 = 0.f;
        #pragma unroll
        for (int ni = 0; ni < 8; ni++) {
            int c0 = 8 * ni + 2 * tr;
            float p0 = __expf(s[ni][0] - nm1);
            float p1 = __expf(s[ni][1] - nm1);
            float p2 = __expf(s[ni][2] - nm2);
            float p3 = __expf(s[ni][3] - nm2);
            rs1 += p0 + p1; rs2 += p2 + p3;
            Ps[r1][c0]     = f2tf32(p0);
            Ps[r1][c0 + 1] = f2tf32(p1);
            Ps[r2][c0]     = f2tf32(p2);
            Ps[r2][c0 + 1] = f2tf32(p3);
        }
        rs1 += __shfl_xor_sync(0xffffffffu, rs1, 1);
        rs1 += __shfl_xor_sync(0xffffffffu, rs1, 2);
        rs2 += __shfl_xor_sync(0xffffffffu, rs2, 1);
        rs2 += __shfl_xor_sync(0xffffffffu, rs2, 2);

        l1 = l1 * a1 + rs1; l2 = l2 * a2 + rs2;
        m1 = nm1; m2 = nm2;

        #pragma unroll
        for (int ni = 0; ni < 16; ni++) {
            o[ni][0] *= a1; o[ni][1] *= a1;
            o[ni][2] *= a2; o[ni][3] *= a2;
        }

        __syncwarp();

        #pragma unroll
        for (int kp = 0; kp < 8; kp++) {
            float a0  = Ps[r1][8 * kp + tr];
            float a1f = Ps[r2][8 * kp + tr];
            float a2f = Ps[r1][8 * kp + tr + 4];
            float a3f = Ps[r2][8 * kp + tr + 4];
            #pragma unroll
            for (int ni = 0; ni < 16; ni++) {
                float b0 = Vs[8 * kp + tr][8 * ni + tq];
                float b1 = Vs[8 * kp + tr + 4][8 * ni + tq];
                mma8(o[ni][0], o[ni][1], o[ni][2], o[ni][3], a0, a1f, a2f, a3f, b0, b1);
            }
        }
    }

    const float inv1 = 1.0f / l1, inv2 = 1.0f / l2;
    #pragma unroll
    for (int ni = 0; ni < 16; ni++) {
        int d = 8 * ni + 2 * tr;
        *(float2*)(g_attn + (size_t)rowg1 * O_N + h * HD + d) =
            make_float2(f2tf32(o[ni][0] * inv1), f2tf32(o[ni][1] * inv1));
        *(float2*)(g_attn + (size_t)rowg2 * O_N + h * HD + d) =
            make_float2(f2tf32(o[ni][2] * inv2), f2tf32(o[ni][3] * inv2));
    }
}

// ---------------------------------------------------------------------------
extern "C" void kernel_launch(void* const* d_in, const int* in_sizes, int n_in,
                              void* d_out, int out_size) {
    const float* hidden = (const float*)d_in[1];
    const float* w_qkv  = (const float*)d_in[2];
    const float* qw     = (const float*)d_in[3];
    const float* kw     = (const float*)d_in[4];
    const float* w_o    = (const float*)d_in[5];
    float* out = (float*)d_out;

    void *qkv_p = nullptr, *attn_p = nullptr, *hidr_p = nullptr;
    void *wqkvr_p = nullptr, *wor_p = nullptr;
    cudaGetSymbolAddress(&qkv_p, g_qkv);
    cudaGetSymbolAddress(&attn_p, g_attn);
    cudaGetSymbolAddress(&hidr_p, g_hidr);
    cudaGetSymbolAddress(&wqkvr_p, g_wqkvr);
    cudaGetSymbolAddress(&wor_p, g_wor);

    static bool init_done = false;
    static cudaStream_t s_side = nullptr;
    static cudaEvent_t ev_fork = nullptr, ev_join = nullptr;
    if (!init_done) {
        cudaFuncSetAttribute(gemm_tf32_pipe,
                             cudaFuncAttributeMaxDynamicSharedMemorySize, GEMM_SMEM);
        cudaFuncSetAttribute(flash_attn,
                             cudaFuncAttributeMaxDynamicSharedMemorySize, ATTN_SMEM);
        cudaStreamCreateWithFlags(&s_side, cudaStreamNonBlocking);
        cudaEventCreateWithFlags(&ev_fork, cudaEventDisableTiming);
        cudaEventCreateWithFlags(&ev_join, cudaEventDisableTiming);
        init_done = true;
    }

    // critical-path prepass for QKV GEMM's A matrix
    round_copy<<<(T_SEQ * HID / 4 + 255) / 256, 256>>>(
        hidden, (float*)hidr_p, T_SEQ * HID / 4);

    // fork early: w_o rounding overlaps w_qkv prepass + QKV GEMM + flash
    cudaEventRecord(ev_fork, 0);
    cudaStreamWaitEvent(s_side, ev_fork, 0);
    round_copy<<<(HID * O_N / 4 + 255) / 256, 256, 0, s_side>>>(
        w_o, (float*)wor_p, HID * O_N / 4);
    cudaEventRecord(ev_join, s_side);

    round_copy<<<(HID * QKV_N / 4 + 255) / 256, 256>>>(
        w_qkv, (float*)wqkvr_p, HID * QKV_N / 4);

    // QKV GEMM with fused RMSNorm+RoPE epilogue
    gemm_tf32_pipe<<<dim3(T_SEQ / BM, QKV_N / BN), 256, GEMM_SMEM>>>(
        (const float*)hidr_p, (const float*)wqkvr_p, (float*)qkv_p,
        T_SEQ, QKV_N, HID, qw, kw, 1);

    flash_attn<<<dim3(NKV, T_SEQ / 32), 256, ATTN_SMEM>>>();

    cudaStreamWaitEvent(0, ev_join, 0);

    gemm_tf32_pipe<<<dim3(T_SEQ / BM, O_N / BN), 256, GEMM_SMEM>>>(
        (const float*)attn_p, (const float*)wor_p, out,
        T_SEQ, O_N, HID, nullptr, nullptr, 0);
}

// round 16
// speedup vs baseline: 1.0955x; 1.0099x over previous
#include <cuda_runtime.h>
#include <cstdint>
#include <math.h>

// ---------------------------------------------------------------------------
// Qwen3 attention block. Round 16: cp.async double-buffered KV in flash.
//   - QKV epilogue stores K (post-RoPE) and V pre-rounded to tf32 -> flash
//     stages raw bytes (no cvt), values bit-identical to before.
//   - flash: smem overlay [Ps | KV0 | regionX(Q then KV1)], cp.async
//     prefetch distance 1, ONE barrier per KV iter (was 2 + exposed LDG).
//   - LPT heavy-first flash order (R15 WIN), fused norm epilogue (R14 WIN),
//     R10 GEMM, side-stream w_o overlap all kept.
// ---------------------------------------------------------------------------

#define T_SEQ 2048
#define HID   4096
#define NQH   32
#define NKV   8
#define HD    128
#define QKV_N 6144
#define O_N   4096

__device__ float g_qkv[(size_t)T_SEQ * QKV_N];
__device__ float g_attn[(size_t)T_SEQ * O_N];
__device__ float g_hidr[(size_t)T_SEQ * HID];
__device__ float g_wqkvr[(size_t)HID * QKV_N];
__device__ float g_wor[(size_t)HID * O_N];

__device__ __forceinline__ float f2tf32(float x) {
    uint32_t u;
    asm("cvt.rna.tf32.f32 %0, %1;" : "=r"(u) : "f"(x));
    return __uint_as_float(u);
}

__device__ __forceinline__ void mma8(float& c0, float& c1, float& c2, float& c3,
                                     float a0, float a1, float a2, float a3,
                                     float b0, float b1) {
    asm volatile(
        "mma.sync.aligned.m16n8k8.row.col.f32.tf32.tf32.f32 "
        "{%0,%1,%2,%3}, {%4,%5,%6,%7}, {%8,%9}, {%0,%1,%2,%3};\n"
        : "+f"(c0), "+f"(c1), "+f"(c2), "+f"(c3)
        : "r"(__float_as_uint(a0)), "r"(__float_as_uint(a1)),
          "r"(__float_as_uint(a2)), "r"(__float_as_uint(a3)),
          "r"(__float_as_uint(b0)), "r"(__float_as_uint(b1)));
}

__device__ __forceinline__ uint32_t s2u(const void* p) {
    return (uint32_t)__cvta_generic_to_shared(p);
}
#define CPASYNC16(dst_u32, src_ptr) \
    asm volatile("cp.async.cg.shared.global [%0], [%1], 16;\n" \
                 :: "r"(dst_u32), "l"(src_ptr))

// ---------------------------------------------------------------------------
// Pipelined GEMM (R10 mainloop): C[M,N] = A[M,K] @ B[K,N], tf32 operands.
// Block 128x256, BK=32, 256 threads, 4-stage cp.async ring, 1 barrier/iter.
// fuse=1 (QKV): epilogue stages tile in smem, applies RMSNorm+RoPE per head;
// K and V regions stored tf32-rounded (flash stages raw).
// ---------------------------------------------------------------------------
#define BM 128
#define BN 256
#define BK 32
#define ASTRD 36
#define BSTRD 264
#define STG_FLOATS (BM * ASTRD + BK * BSTRD)            // 13056
#define GEMM_SMEM (4 * STG_FLOATS * 4)                  // 208896 B
#define CSTRD 264

__global__ __launch_bounds__(256, 1)
void gemm_tf32_pipe(const float* __restrict__ A, const float* __restrict__ B,
                    float* __restrict__ C, int M, int N, int K,
                    const float* __restrict__ qw, const float* __restrict__ kw,
                    int fuse) {
    extern __shared__ float sm[];

    const int tid  = threadIdx.x;
    const int warp = tid >> 5, lane = tid & 31;
    const int tq = lane >> 2, tr = lane & 3;
    const int wm = (warp & 1) * 64;
    const int wn = (warp >> 1) * 64;
    const size_t bm = (size_t)blockIdx.x * BM;
    const size_t bn = (size_t)blockIdx.y * BN;

    float c[4][8][4];
    #pragma unroll
    for (int mi = 0; mi < 4; mi++)
        #pragma unroll
        for (int ni = 0; ni < 8; ni++)
            #pragma unroll
            for (int e = 0; e < 4; e++) c[mi][ni][e] = 0.f;

    const int arow = tid >> 3, acol = (tid & 7) * 4;
    const int brow = tid >> 6, bcol = (tid & 63) * 4;
    const int NT = K / BK;

    auto stage = [&](int kt, int s) {
        float* sa = sm + s * STG_FLOATS;
        float* sb = sa + BM * ASTRD;
        #pragma unroll
        for (int i = 0; i < 4; i++)
            CPASYNC16(s2u(sa + (arow + 32 * i) * ASTRD + acol),
                      A + (bm + arow + 32 * i) * (size_t)K + kt + acol);
        #pragma unroll
        for (int i = 0; i < 8; i++)
            CPASYNC16(s2u(sb + (brow + 4 * i) * BSTRD + bcol),
                      B + (size_t)(kt + brow + 4 * i) * N + bn + bcol);
        asm volatile("cp.async.commit_group;\n");
    };

    stage(0, 0);
    stage(BK, 1);

    for (int t = 0; t < NT; t++) {
        if (t + 2 < NT) {
            stage((t + 2) * BK, (t + 2) & 3);
            asm volatile("cp.async.wait_group 2;\n");
        } else if (t + 1 < NT) {
            asm volatile("cp.async.wait_group 1;\n");
        } else {
            asm volatile("cp.async.wait_group 0;\n");
        }
        __syncthreads();

        const float* sa = sm + (t & 3) * STG_FLOATS;
        const float* sb = sa + BM * ASTRD;

        #pragma unroll
        for (int kk = 0; kk < 4; kk++) {
            const int k0 = 8 * kk + tr;
            float a[4][4];
            #pragma unroll
            for (int mi = 0; mi < 4; mi++) {
                const int r0 = wm + 16 * mi + tq;
                a[mi][0] = sa[r0 * ASTRD + k0];
                a[mi][1] = sa[(r0 + 8) * ASTRD + k0];
                a[mi][2] = sa[r0 * ASTRD + k0 + 4];
                a[mi][3] = sa[(r0 + 8) * ASTRD + k0 + 4];
            }
            float b[8][2];
            #pragma unroll
            for (int ni = 0; ni < 8; ni++) {
                const int col = wn + 8 * ni + tq;
                b[ni][0] = sb[k0 * BSTRD + col];
                b[ni][1] = sb[(k0 + 4) * BSTRD + col];
            }
            #pragma unroll
            for (int mi = 0; mi < 4; mi++)
                #pragma unroll
                for (int ni = 0; ni < 8; ni++)
                    mma8(c[mi][ni][0], c[mi][ni][1], c[mi][ni][2], c[mi][ni][3],
                         a[mi][0], a[mi][1], a[mi][2], a[mi][3],
                         b[ni][0], b[ni][1]);
        }
    }

    if (!fuse) {
        #pragma unroll
        for (int mi = 0; mi < 4; mi++) {
            #pragma unroll
            for (int ni = 0; ni < 8; ni++) {
                size_t r  = bm + wm + 16 * mi + tq;
                size_t cc = bn + wn + 8 * ni + 2 * tr;
                *(float2*)(C + r * N + cc)       = make_float2(c[mi][ni][0], c[mi][ni][1]);
                *(float2*)(C + (r + 8) * N + cc) = make_float2(c[mi][ni][2], c[mi][ni][3]);
            }
        }
        return;
    }

    // ---- fused epilogue: RMSNorm+RoPE; K/V stored tf32-rounded ----
    __syncthreads();
    float (*Cs)[CSTRD] = (float(*)[CSTRD])sm;
    #pragma unroll
    for (int mi = 0; mi < 4; mi++) {
        #pragma unroll
        for (int ni = 0; ni < 8; ni++) {
            int r  = wm + 16 * mi + tq;
            int cc = wn + 8 * ni + 2 * tr;
            *(float2*)&Cs[r][cc]     = make_float2(c[mi][ni][0], c[mi][ni][1]);
            *(float2*)&Cs[r + 8][cc] = make_float2(c[mi][ni][2], c[mi][ni][3]);
        }
    }
    __syncthreads();

    const int gh0 = (int)(bn >> 7);
    for (int it = 0; it < 32; it++) {
        const int p   = warp * 32 + it;
        const int row = p & 127;
        const int hl  = p >> 7;
        const int gh  = gh0 + hl;
        const float* src = &Cs[row][hl * HD];
        float* dst = C + (bm + row) * (size_t)N + bn + hl * HD;

        float v0 = src[lane];
        float v1 = src[lane + 32];
        float v2 = src[lane + 64];
        float v3 = src[lane + 96];

        if (gh >= NQH + NKV) {                 // v region: tf32-rounded store
            dst[lane]      = f2tf32(v0);
            dst[lane + 32] = f2tf32(v1);
            dst[lane + 64] = f2tf32(v2);
            dst[lane + 96] = f2tf32(v3);
        } else {
            float ss = v0 * v0 + v1 * v1 + v2 * v2 + v3 * v3;
            #pragma unroll
            for (int o = 16; o > 0; o >>= 1) ss += __shfl_xor_sync(0xffffffffu, ss, o);
            float scale = rsqrtf(ss * (1.0f / HD) + 1e-6f);
            const float* wv = (gh < NQH) ? qw : kw;
            float x1a = v0 * scale * wv[lane];
            float x2a = v2 * scale * wv[lane + 64];
            float x1b = v1 * scale * wv[lane + 32];
            float x2b = v3 * scale * wv[lane + 96];
            float tpos = (float)(bm + row);
            float ia = exp2f(-(float)lane        * (19.931568569324174f / 64.0f));
            float ib = exp2f(-(float)(lane + 32) * (19.931568569324174f / 64.0f));
            float sa_, ca_, sb_, cb_;
            sincosf(tpos * ia, &sa_, &ca_);
            sincosf(tpos * ib, &sb_, &cb_);
            float o0 = x1a * ca_ - x2a * sa_;
            float o2 = x2a * ca_ + x1a * sa_;
            float o1 = x1b * cb_ - x2b * sb_;
            float o3 = x2b * cb_ + x1b * sb_;
            if (gh >= NQH) {                   // k region: tf32-rounded store
                o0 = f2tf32(o0); o1 = f2tf32(o1);
                o2 = f2tf32(o2); o3 = f2tf32(o3);
            }
            dst[lane]      = o0;
            dst[lane + 64] = o2;
            dst[lane + 32] = o1;
            dst[lane + 96] = o3;
        }
    }
}

// ---------------------------------------------------------------------------
// prepass: elementwise tf32 rounding
// ---------------------------------------------------------------------------
__global__ void round_copy(const float* __restrict__ src, float* __restrict__ dst,
                           int n4) {
    int i = blockIdx.x * blockDim.x + threadIdx.x;
    if (i < n4) {
        float4 v = ((const float4*)src)[i];
        v.x = f2tf32(v.x); v.y = f2tf32(v.y); v.z = f2tf32(v.z); v.w = f2tf32(v.w);
        ((float4*)dst)[i] = v;
    }
}

// ---------------------------------------------------------------------------
// GQA flash attention, cp.async double-buffered KV, LPT order.
// smem overlay (floats): [Ps 8704 | KV0 17152 | regionX 17152]
//   regionX holds Q (16896) during prologue, then KV1.
//   KV buffer: K 64x132 then V 64x136.
// ---------------------------------------------------------------------------
#define QSTR 132
#define KSTR 132
#define VSTR 136
#define PSTR 68
#define PS_FLOATS   (128 * PSTR)               // 8704
#define KV_FLOATS   (64 * KSTR + 64 * VSTR)    // 17152
#define ATTN_SMEM   ((PS_FLOATS + 2 * KV_FLOATS) * 4)   // 172032 B

__global__ __launch_bounds__(256, 1)
void flash_attn() {
    extern __shared__ float sm[];
    float (*Ps)[PSTR] = (float(*)[PSTR])sm;
    float* kv0 = sm + PS_FLOATS;
    float* kv1 = sm + PS_FLOATS + KV_FLOATS;   // regionX (Q first, then KV1)
    float* Qsp = kv1;

    const int kh = blockIdx.x;
    const int qb = (T_SEQ / 32 - 1) - blockIdx.y;   // heavy-first (LPT)
    const int tid = threadIdx.x;
    const int w = tid >> 5, lane = tid & 31;
    const int tq = lane >> 2, tr = lane & 3;
    const int hl = w >> 1;
    const int h  = 4 * kh + hl;
    const int wrow = (w & 1) * 16;
    const float scaling = 0.08838834764831845f;
    const int kb_last = (32 * qb + 31) >> 6;

    // cp.async staging of one KV buffer (K and V pre-rounded at source)
    auto stage_kv = [&](int kb, float* buf) {
        float* Kb = buf;
        float* Vb = buf + 64 * KSTR;
        #pragma unroll
        for (int i = 0; i < 8; i++) {
            int f = tid + 256 * i;
            int row = f >> 5, c4 = (f & 31) * 4;
            const float* rp = g_qkv + (size_t)(64 * kb + row) * QKV_N + kh * HD + c4;
            CPASYNC16(s2u(Kb + row * KSTR + c4), rp + 4096);
            CPASYNC16(s2u(Vb + row * VSTR + c4), rp + 5120);
        }
        asm volatile("cp.async.commit_group;\n");
    };

    // prologue: prefetch KV0 while staging Q synchronously into regionX
    stage_kv(0, kv0);
    #pragma unroll
    for (int i = 0; i < 16; i++) {
        int f = tid + 256 * i;
        int head = f >> 10;
        int row  = (f >> 5) & 31;
        int c4   = (f & 31) * 4;
        float4 v = *(const float4*)(g_qkv + (size_t)(32 * qb + row) * QKV_N
                                    + (4 * kh + head) * HD + c4);
        v.x = f2tf32(v.x * scaling); v.y = f2tf32(v.y * scaling);
        v.z = f2tf32(v.z * scaling); v.w = f2tf32(v.w * scaling);
        *(float4*)&Qsp[head * 32 * QSTR + row * QSTR + c4] = v;
    }
    __syncthreads();

    float qf[16][4];
    const float* qbase = Qsp + hl * 32 * QSTR;
    #pragma unroll
    for (int kk = 0; kk < 16; kk++) {
        int r0 = wrow + tq, k0 = 8 * kk + tr;
        qf[kk][0] = qbase[r0 * QSTR + k0];
        qf[kk][1] = qbase[(r0 + 8) * QSTR + k0];
        qf[kk][2] = qbase[r0 * QSTR + k0 + 4];
        qf[kk][3] = qbase[(r0 + 8) * QSTR + k0 + 4];
    }
    asm volatile("cp.async.wait_group 0;\n");   // KV0 landed (per-thread)
    __syncthreads();                            // Q reads done; KV0 published

    float o[16][4];
    #pragma unroll
    for (int ni = 0; ni < 16; ni++)
        #pragma unroll
        for (int e = 0; e < 4; e++) o[ni][e] = 0.f;
    float m1 = -1e30f, m2 = -1e30f, l1 = 0.f, l2 = 0.f;

    const int r1 = 16 * w + tq, r2 = r1 + 8;
    const int rowg1 = 32 * qb + wrow + tq;
    const int rowg2 = rowg1 + 8;

    for (int kb = 0; kb <= kb_last; kb++) {
        if (kb > 0) {
            asm volatile("cp.async.wait_group 0;\n");   // KV(kb) landed
            __syncthreads();     // publish KV(kb); all warps past compute(kb-1)
        }
        // prefetch kb+1 into the buffer freed by compute(kb-1) (or regionX at kb=0)
        if (kb + 1 <= kb_last)
            stage_kv(kb + 1, ((kb + 1) & 1) ? kv1 : kv0);

        const float* Kb = (kb & 1) ? kv1 : kv0;
        const float* Vb = Kb + 64 * KSTR;

        float s[8][4];
        #pragma unroll
        for (int ni = 0; ni < 8; ni++)
            #pragma unroll
            for (int e = 0; e < 4; e++) s[ni][e] = 0.f;

        #pragma unroll
        for (int kk = 0; kk < 16; kk++) {
            const int d0 = 8 * kk + tr;
            #pragma unroll
            for (int ni = 0; ni < 8; ni++) {
                float b0 = Kb[(8 * ni + tq) * KSTR + d0];
                float b1 = Kb[(8 * ni + tq) * KSTR + d0 + 4];
                mma8(s[ni][0], s[ni][1], s[ni][2], s[ni][3],
                     qf[kk][0], qf[kk][1], qf[kk][2], qf[kk][3], b0, b1);
            }
        }

        if (kb == kb_last) {
            #pragma unroll
            for (int ni = 0; ni < 8; ni++) {
                int c0g = 64 * kb + 8 * ni + 2 * tr;
                if (c0g     > rowg1) s[ni][0] = -1e30f;
                if (c0g + 1 > rowg1) s[ni][1] = -1e30f;
                if (c0g     > rowg2) s[ni][2] = -1e30f;
                if (c0g + 1 > rowg2) s[ni][3] = -1e30f;
            }
        }

        float tm1 = -1e30f, tm2 = -1e30f;
        #pragma unroll
        for (int ni = 0; ni < 8; ni++) {
            tm1 = fmaxf(tm1, fmaxf(s[ni][0], s[ni][1]));
            tm2 = fmaxf(tm2, fmaxf(s[ni][2], s[ni][3]));
        }
        tm1 = fmaxf(tm1, __shfl_xor_sync(0xffffffffu, tm1, 1));
        tm1 = fmaxf(tm1, __shfl_xor_sync(0xffffffffu, tm1, 2));
        tm2 = fmaxf(tm2, __shfl_xor_sync(0xffffffffu, tm2, 1));
        tm2 = fmaxf(tm2, __shfl_xor_sync(0xffffffffu, tm2, 2));

        float nm1 = fmaxf(m1, tm1), nm2 = fmaxf(m2, tm2);
        float a1 = __expf(m1 - nm1), a2 = __expf(m2 - nm2);

        float rs1 = 0.f, rs2 = 0.f;
        #pragma unroll
        for (int ni = 0; ni < 8; ni++) {
            int c0 = 8 * ni + 2 * tr;
            float p0 = __expf(s[ni][0] - nm1);
            float p1 = __expf(s[ni][1] - nm1);
            float p2 = __expf(s[ni][2] - nm2);
            float p3 = __expf(s[ni][3] - nm2);
            rs1 += p0 + p1; rs2 += p2 + p3;
            Ps[r1][c0]     = f2tf32(p0);
            Ps[r1][c0 + 1] = f2tf32(p1);
            Ps[r2][c0]     = f2tf32(p2);
            Ps[r2][c0 + 1] = f2tf32(p3);
        }
        rs1 += __shfl_xor_sync(0xffffffffu, rs1, 1);
        rs1 += __shfl_xor_sync(0xffffffffu, rs1, 2);
        rs2 += __shfl_xor_sync(0xffffffffu, rs2, 1);
        rs2 += __shfl_xor_sync(0xffffffffu, rs2, 2);

        l1 = l1 * a1 + rs1; l2 = l2 * a2 + rs2;
        m1 = nm1; m2 = nm2;

        #pragma unroll
        for (int ni = 0; ni < 16; ni++) {
            o[ni][0] *= a1; o[ni][1] *= a1;
            o[ni][2] *= a2; o[ni][3] *= a2;
        }

        __syncwarp();

        #pragma unroll
        for (int kp = 0; kp < 8; kp++) {
            float a0  = Ps[r1][8 * kp + tr];
            float a1f = Ps[r2][8 * kp + tr];
            float a2f = Ps[r1][8 * kp + tr + 4];
            float a3f = Ps[r2][8 * kp + tr + 4];
            #pragma unroll
            for (int ni = 0; ni < 16; ni++) {
                float b0 = Vb[(8 * kp + tr) * VSTR + 8 * ni + tq];
                float b1 = Vb[(8 * kp + tr + 4) * VSTR + 8 * ni + tq];
                mma8(o[ni][0], o[ni][1], o[ni][2], o[ni][3], a0, a1f, a2f, a3f, b0, b1);
            }
        }
    }

    const float inv1 = 1.0f / l1, inv2 = 1.0f / l2;
    #pragma unroll
    for (int ni = 0; ni < 16; ni++) {
        int d = 8 * ni + 2 * tr;
        *(float2*)(g_attn + (size_t)rowg1 * O_N + h * HD + d) =
            make_float2(f2tf32(o[ni][0] * inv1), f2tf32(o[ni][1] * inv1));
        *(float2*)(g_attn + (size_t)rowg2 * O_N + h * HD + d) =
            make_float2(f2tf32(o[ni][2] * inv2), f2tf32(o[ni][3] * inv2));
    }
}

// ---------------------------------------------------------------------------
extern "C" void kernel_launch(void* const* d_in, const int* in_sizes, int n_in,
                              void* d_out, int out_size) {
    const float* hidden = (const float*)d_in[1];
    const float* w_qkv  = (const float*)d_in[2];
    const float* qw     = (const float*)d_in[3];
    const float* kw     = (const float*)d_in[4];
    const float* w_o    = (const float*)d_in[5];
    float* out = (float*)d_out;

    void *qkv_p = nullptr, *attn_p = nullptr, *hidr_p = nullptr;
    void *wqkvr_p = nullptr, *wor_p = nullptr;
    cudaGetSymbolAddress(&qkv_p, g_qkv);
    cudaGetSymbolAddress(&attn_p, g_attn);
    cudaGetSymbolAddress(&hidr_p, g_hidr);
    cudaGetSymbolAddress(&wqkvr_p, g_wqkvr);
    cudaGetSymbolAddress(&wor_p, g_wor);

    static bool init_done = false;
    static cudaStream_t s_side = nullptr;
    static cudaEvent_t ev_fork = nullptr, ev_join = nullptr;
    if (!init_done) {
        cudaFuncSetAttribute(gemm_tf32_pipe,
                             cudaFuncAttributeMaxDynamicSharedMemorySize, GEMM_SMEM);
        cudaFuncSetAttribute(flash_attn,
                             cudaFuncAttributeMaxDynamicSharedMemorySize, ATTN_SMEM);
        cudaStreamCreateWithFlags(&s_side, cudaStreamNonBlocking);
        cudaEventCreateWithFlags(&ev_fork, cudaEventDisableTiming);
        cudaEventCreateWithFlags(&ev_join, cudaEventDisableTiming);
        init_done = true;
    }

    round_copy<<<(T_SEQ * HID / 4 + 255) / 256, 256>>>(
        hidden, (float*)hidr_p, T_SEQ * HID / 4);

    cudaEventRecord(ev_fork, 0);
    cudaStreamWaitEvent(s_side, ev_fork, 0);
    round_copy<<<(HID * O_N / 4 + 255) / 256, 256, 0, s_side>>>(
        w_o, (float*)wor_p, HID * O_N / 4);
    cudaEventRecord(ev_join, s_side);

    round_copy<<<(HID * QKV_N / 4 + 255) / 256, 256>>>(
        w_qkv, (float*)wqkvr_p, HID * QKV_N / 4);

    gemm_tf32_pipe<<<dim3(T_SEQ / BM, QKV_N / BN), 256, GEMM_SMEM>>>(
        (const float*)hidr_p, (const float*)wqkvr_p, (float*)qkv_p,
        T_SEQ, QKV_N, HID, qw, kw, 1);

    flash_attn<<<dim3(NKV, T_SEQ / 32), 256, ATTN_SMEM>>>();

    cudaStreamWaitEvent(0, ev_join, 0);

    gemm_tf32_pipe<<<dim3(T_SEQ / BM, O_N / BN), 256, GEMM_SMEM>>>(
        (const float*)attn_p, (const float*)wor_p, out,
        T_SEQ, O_N, HID, nullptr, nullptr, 0);
}